// round 15
// baseline (speedup 1.0000x reference)
#include <cuda_runtime.h>

// ---------------- problem constants ----------------
#define NB   8
#define NT   24
#define NN   263
#define ND   512
#define NBT  192          // B*T
#define NBTN 50496        // B*T*N
#define LDQ  1408         // packed qkv width

// packed QKV column offsets
#define C_QS   0
#define C_KS   256
#define C_VS   512
#define C_QT   768
#define C_KT   896
#define C_VT   1024
#define C_KTG  1152
#define C_VTG  1280

// ---------------- scratch (device globals; no allocation) ----------------
__device__ float g_W  [1408 * 512];
__device__ float g_Wa0[384 * 512];
__device__ float g_Wa1[384 * 512];
__device__ float g_QKV [(size_t)NBTN * LDQ];          // 284 MB
__device__ float g_AGP0[(size_t)NBT * 32 * 384];
__device__ float g_AGP1[(size_t)NBT * 64 * 384];
__device__ float g_ADIFF[(size_t)NBTN * 512];         // [btn][h(4)][br(2)][64]
__device__ float g_SX0[(size_t)NBT * 4096];           // [bt][h(2)][m(32)][64]
__device__ float g_SX1[(size_t)NBT * 8192];           // [bt][h(2)][m(64)][64]
__device__ float g_SGP[(size_t)NBTN * 128];
__device__ float g_ST [(size_t)NBTN * 640];           // 129 MB
__device__ float g_lambda;

// ---------------- lambda scalar ----------------
__global__ void lambda_kernel(const float* __restrict__ lq1, const float* __restrict__ lk1,
                              const float* __restrict__ lq2, const float* __restrict__ lk2) {
    int l = threadIdx.x;
    float a = lq1[l] * lk1[l];
    float b = lq2[l] * lk2[l];
    #pragma unroll
    for (int o = 16; o; o >>= 1) {
        a += __shfl_xor_sync(0xffffffffu, a, o);
        b += __shfl_xor_sync(0xffffffffu, b, o);
    }
    if (l == 0) g_lambda = expf(a) - expf(b) + 0.2f;   // LAMBDA_INIT = 0.2
}

// ---------------- generic SGEMM: C[M,Nc] = A[M,K] * B[Nc,K]^T (+bias) ----------------
// BM=BN=128, BK=16, 256 threads, 8x8 micro-tile. K % 16 == 0 required (true for 512/128/640).
__global__ __launch_bounds__(256) void sgemm_nt(
    const float* __restrict__ A, int lda,
    const float* __restrict__ Bw, int ldb,
    float* __restrict__ C, int ldc,
    int M, int Ncols, int K,
    const float* __restrict__ bias)
{
    __shared__ float As[16][132];
    __shared__ float Bs[16][132];
    const int tid = threadIdx.x;
    const int bm = blockIdx.x * 128;
    const int bn = blockIdx.y * 128;
    const int tx = tid & 15, ty = tid >> 4;

    float acc[8][8];
    #pragma unroll
    for (int i = 0; i < 8; i++)
        #pragma unroll
        for (int j = 0; j < 8; j++) acc[i][j] = 0.f;

    for (int k0 = 0; k0 < K; k0 += 16) {
        #pragma unroll
        for (int l = 0; l < 2; l++) {
            int i = tid + l * 256;
            int row = i >> 2;
            int kq  = (i & 3) << 2;
            float4 v = make_float4(0.f, 0.f, 0.f, 0.f);
            int gr = bm + row;
            if (gr < M) v = *(const float4*)&A[(size_t)gr * lda + k0 + kq];
            As[kq + 0][row] = v.x; As[kq + 1][row] = v.y;
            As[kq + 2][row] = v.z; As[kq + 3][row] = v.w;
        }
        #pragma unroll
        for (int l = 0; l < 2; l++) {
            int i = tid + l * 256;
            int col = i >> 2;
            int kq  = (i & 3) << 2;
            float4 v = make_float4(0.f, 0.f, 0.f, 0.f);
            int gc = bn + col;
            if (gc < Ncols) v = *(const float4*)&Bw[(size_t)gc * ldb + k0 + kq];
            Bs[kq + 0][col] = v.x; Bs[kq + 1][col] = v.y;
            Bs[kq + 2][col] = v.z; Bs[kq + 3][col] = v.w;
        }
        __syncthreads();
        #pragma unroll
        for (int k = 0; k < 16; k++) {
            float4 a0 = *(const float4*)&As[k][ty * 8];
            float4 a1 = *(const float4*)&As[k][ty * 8 + 4];
            float4 b0 = *(const float4*)&Bs[k][tx * 8];
            float4 b1 = *(const float4*)&Bs[k][tx * 8 + 4];
            float av[8] = {a0.x, a0.y, a0.z, a0.w, a1.x, a1.y, a1.z, a1.w};
            float bv[8] = {b0.x, b0.y, b0.z, b0.w, b1.x, b1.y, b1.z, b1.w};
            #pragma unroll
            for (int i = 0; i < 8; i++)
                #pragma unroll
                for (int j = 0; j < 8; j++) acc[i][j] += av[i] * bv[j];
        }
        __syncthreads();
    }

    float bsv[8];
    #pragma unroll
    for (int j = 0; j < 8; j++) {
        int col = bn + tx * 8 + j;
        bsv[j] = (bias != nullptr && col < Ncols) ? bias[col] : 0.f;
    }
    #pragma unroll
    for (int i = 0; i < 8; i++) {
        int row = bm + ty * 8 + i;
        if (row >= M) continue;
        float* cp = &C[(size_t)row * ldc + bn + tx * 8];
        if (bn + tx * 8 + 7 < Ncols) {
            float4 o0 = make_float4(acc[i][0] + bsv[0], acc[i][1] + bsv[1],
                                    acc[i][2] + bsv[2], acc[i][3] + bsv[3]);
            float4 o1 = make_float4(acc[i][4] + bsv[4], acc[i][5] + bsv[5],
                                    acc[i][6] + bsv[6], acc[i][7] + bsv[7]);
            *(float4*)cp       = o0;
            *(float4*)(cp + 4) = o1;
        } else {
            #pragma unroll
            for (int j = 0; j < 8; j++) {
                int col = bn + tx * 8 + j;
                if (col < Ncols) cp[j] = acc[i][j] + bsv[j];
            }
        }
    }
}

// ---------------- differential spatial attention ----------------
// grid (NBT, 4 heads, 2 branches), 256 threads, dyn smem: K(263*32)+V(263*64) floats.
__global__ __launch_bounds__(256) void spatial_attn()
{
    extern __shared__ float sh[];
    float* Ksh = sh;             // 263*32
    float* Vsh = sh + NN * 32;   // 263*64
    const int bt = blockIdx.x, h = blockIdx.y, br = blockIdx.z;
    const int tid = threadIdx.x;
    const size_t base = (size_t)bt * NN * LDQ;
    const int kcol = C_KS + h * 64 + br * 32;
    const int vcol = C_VS + h * 64;
    const int qcol = C_QS + h * 64 + br * 32;

    for (int i = tid; i < NN * 32; i += 256) {
        int n = i >> 5, d = i & 31;
        Ksh[i] = g_QKV[base + (size_t)n * LDQ + kcol + d];
    }
    for (int i = tid; i < NN * 64; i += 256) {
        int n = i >> 6, d = i & 63;
        Vsh[i] = g_QKV[base + (size_t)n * LDQ + vcol + d];
    }
    __syncthreads();

    const float sc = 0.17677669529663687f;  // 32^-0.5
    for (int qi = tid; qi < NN; qi += 256) {
        float4 q[8];
        const float4* qp = (const float4*)&g_QKV[base + (size_t)qi * LDQ + qcol];
        #pragma unroll
        for (int j = 0; j < 8; j++) q[j] = qp[j];

        float4 acc[16];
        #pragma unroll
        for (int j = 0; j < 16; j++) acc[j] = make_float4(0.f, 0.f, 0.f, 0.f);
        float s = 0.f;

        for (int key = 0; key < NN; key++) {
            const float4* kp = (const float4*)&Ksh[key * 32];
            float dot = 0.f;
            #pragma unroll
            for (int j = 0; j < 8; j++) {
                float4 kv = kp[j];
                dot += q[j].x * kv.x + q[j].y * kv.y + q[j].z * kv.z + q[j].w * kv.w;
            }
            float p = __expf(dot * sc);
            s += p;
            const float4* vp = (const float4*)&Vsh[key * 64];
            #pragma unroll
            for (int j = 0; j < 16; j++) {
                float4 vv = vp[j];
                acc[j].x += p * vv.x; acc[j].y += p * vv.y;
                acc[j].z += p * vv.z; acc[j].w += p * vv.w;
            }
        }
        float inv = 1.f / s;
        float* o = &g_ADIFF[(((size_t)(bt * NN + qi) * 4 + h) * 2 + br) * 64];
        #pragma unroll
        for (int j = 0; j < 16; j++) {
            float4 ov = make_float4(acc[j].x * inv, acc[j].y * inv,
                                    acc[j].z * inv, acc[j].w * inv);
            *(float4*)&o[j * 4] = ov;
        }
    }
}

// ---------------- combine a1 - lam*a2, LayerNorm(64), *0.8 -> ST[:,0:256] ----------------
__global__ __launch_bounds__(256) void combine_ln(const float* __restrict__ lng,
                                                  const float* __restrict__ lnb)
{
    int gw = (blockIdx.x * 256 + threadIdx.x) >> 5;
    int lane = threadIdx.x & 31;
    if (gw >= NBTN * 4) return;
    const float* a = &g_ADIFF[(size_t)gw * 128];
    float lam = g_lambda;
    float y0 = a[lane]      - lam * a[lane + 64];
    float y1 = a[lane + 32] - lam * a[lane + 96];
    float s = y0 + y1, q = y0 * y0 + y1 * y1;
    #pragma unroll
    for (int o = 16; o; o >>= 1) {
        s += __shfl_xor_sync(0xffffffffu, s, o);
        q += __shfl_xor_sync(0xffffffffu, q, o);
    }
    float m   = s * (1.f / 64.f);
    float var = q * (1.f / 64.f) - m * m;
    float r   = rsqrtf(var + 1e-5f);
    int btn = gw >> 2, h = gw & 3;
    float* o = &g_ST[(size_t)btn * 640 + h * 64];
    o[lane]      = ((y0 - m) * r * lng[lane]      + lnb[lane])      * 0.8f;
    o[lane + 32] = ((y1 - m) * r * lng[lane + 32] + lnb[lane + 32]) * 0.8f;
}

// ---------------- aggregate-branch attention (Ni keys/queries, dha=64) ----------------
__global__ __launch_bounds__(64) void agg_attn(const float* __restrict__ AGP,
                                               float* __restrict__ SX, int Ni)
{
    __shared__ float Ksh[64 * 64];
    __shared__ float Vsh[64 * 64];
    const int bt = blockIdx.x, h = blockIdx.y, tid = threadIdx.x;
    const size_t base = (size_t)bt * Ni * 384;
    for (int i = tid; i < Ni * 64; i += 64) {
        int m = i >> 6, d = i & 63;
        Ksh[i] = AGP[base + (size_t)m * 384 + 128 + h * 64 + d];
        Vsh[i] = AGP[base + (size_t)m * 384 + 256 + h * 64 + d];
    }
    __syncthreads();
    if (tid < Ni) {
        float4 q[16];
        const float4* qp = (const float4*)&AGP[base + (size_t)tid * 384 + h * 64];
        #pragma unroll
        for (int j = 0; j < 16; j++) q[j] = qp[j];
        float4 acc[16];
        #pragma unroll
        for (int j = 0; j < 16; j++) acc[j] = make_float4(0.f, 0.f, 0.f, 0.f);
        float s = 0.f;
        for (int key = 0; key < Ni; key++) {
            const float4* kp = (const float4*)&Ksh[key * 64];
            float dot = 0.f;
            #pragma unroll
            for (int j = 0; j < 16; j++) {
                float4 kv = kp[j];
                dot += q[j].x * kv.x + q[j].y * kv.y + q[j].z * kv.z + q[j].w * kv.w;
            }
            float p = __expf(dot * 0.125f);
            s += p;
            const float4* vp = (const float4*)&Vsh[key * 64];
            #pragma unroll
            for (int j = 0; j < 16; j++) {
                float4 vv = vp[j];
                acc[j].x += p * vv.x; acc[j].y += p * vv.y;
                acc[j].z += p * vv.z; acc[j].w += p * vv.w;
            }
        }
        float inv = 1.f / s;
        float* o = &SX[((size_t)(bt * 2 + h) * Ni + tid) * 64];
        #pragma unroll
        for (int j = 0; j < 16; j++)
            *(float4*)&o[j * 4] = make_float4(acc[j].x * inv, acc[j].y * inv,
                                              acc[j].z * inv, acc[j].w * inv);
    }
}

// ---------------- map agg branches to N via M0/M1 -> SGP ----------------
__global__ __launch_bounds__(256) void agg_map(const float* __restrict__ M0,
                                               const float* __restrict__ M1)
{
    __shared__ float s0[4096];
    __shared__ float s1[8192];
    const int bt = blockIdx.x, tid = threadIdx.x;
    const float* src0 = g_SX0 + (size_t)bt * 4096;
    const float* src1 = g_SX1 + (size_t)bt * 8192;
    for (int i = tid; i < 4096; i += 256) s0[i] = src0[i];
    for (int i = tid; i < 8192; i += 256) s1[i] = src1[i];
    __syncthreads();
    for (int g = tid; g < NN * 32; g += 256) {
        int n = g >> 5;
        int c = (g & 31) << 2;   // 0..124, 4-wide groups (never straddle h)
        int h = c >> 6, d = c & 63;
        float4 acc = make_float4(0.f, 0.f, 0.f, 0.f);
        const float* p0 = &s0[h * 2048 + d];
        #pragma unroll
        for (int m = 0; m < 32; m++) {
            float w = M0[m * NN + n];
            float4 v = *(const float4*)&p0[m * 64];
            acc.x += w * v.x; acc.y += w * v.y; acc.z += w * v.z; acc.w += w * v.w;
        }
        const float* p1 = &s1[h * 4096 + d];
        #pragma unroll
        for (int m = 0; m < 64; m++) {
            float w = M1[m * NN + n];
            float4 v = *(const float4*)&p1[m * 64];
            acc.x += w * v.x; acc.y += w * v.y; acc.z += w * v.z; acc.w += w * v.w;
        }
        *(float4*)&g_SGP[(size_t)(bt * NN + n) * 128 + c] = acc;
    }
}

// ---------------- temporal attention over T=24 -> ST[:,384:512] ----------------
__global__ __launch_bounds__(128) void temporal_attn()
{
    __shared__ float Q[24 * 64], K[24 * 64], V[24 * 64], P[24 * 24], Pinv[24];
    const int b = blockIdx.x / NN, n = blockIdx.x % NN, h = blockIdx.y;
    const int tid = threadIdx.x;
    for (int i = tid; i < 24 * 64; i += 128) {
        int t = i >> 6, d = i & 63;
        size_t row = ((size_t)(b * NT + t) * NN + n) * LDQ;
        Q[i] = g_QKV[row + C_QT + h * 64 + d];
        K[i] = g_QKV[row + C_KT + h * 64 + d];
        V[i] = g_QKV[row + C_VT + h * 64 + d];
    }
    __syncthreads();
    for (int i = tid; i < 576; i += 128) {
        int tq = i / 24, ts = i % 24;
        const float4* qp = (const float4*)&Q[tq * 64];
        const float4* kp = (const float4*)&K[ts * 64];
        float dot = 0.f;
        #pragma unroll
        for (int j = 0; j < 16; j++) {
            float4 a = qp[j], c = kp[j];
            dot += a.x * c.x + a.y * c.y + a.z * c.z + a.w * c.w;
        }
        P[i] = __expf(dot * 0.125f);
    }
    __syncthreads();
    if (tid < 24) {
        float s = 0.f;
        #pragma unroll
        for (int j = 0; j < 24; j++) s += P[tid * 24 + j];
        Pinv[tid] = 1.f / s;
    }
    __syncthreads();
    for (int i = tid; i < 1536; i += 128) {
        int tq = i >> 6, d = i & 63;
        float acc = 0.f;
        #pragma unroll
        for (int s = 0; s < 24; s++) acc += P[tq * 24 + s] * V[s * 64 + d];
        g_ST[((size_t)(b * NT + tq) * NN + n) * 640 + 384 + h * 64 + d] = acc * Pinv[tq];
    }
}

// ---------------- temporal aggregation tg -> ST[:,512:640] ----------------
__global__ __launch_bounds__(128) void tg_attn(const float* __restrict__ q_agg,
                                               const float* __restrict__ tmp_map)
{
    __shared__ float Qg[12 * 64], K[24 * 64], V[24 * 64], P[12 * 24], TGX[12 * 64], Pinv[12];
    const int b = blockIdx.x / NN, n = blockIdx.x % NN, h = blockIdx.y;
    const int tid = threadIdx.x;
    for (int i = tid; i < 24 * 64; i += 128) {
        int t = i >> 6, d = i & 63;
        size_t row = ((size_t)(b * NT + t) * NN + n) * LDQ;
        K[i] = g_QKV[row + C_KTG + h * 64 + d];
        V[i] = g_QKV[row + C_VTG + h * 64 + d];
    }
    for (int i = tid; i < 12 * 64; i += 128) {
        int s = i >> 6, d = i & 63;
        Qg[i] = q_agg[((size_t)n * 12 + s) * 128 + h * 64 + d];
    }
    __syncthreads();
    for (int i = tid; i < 288; i += 128) {
        int s = i / 24, t = i % 24;
        const float4* qp = (const float4*)&Qg[s * 64];
        const float4* kp = (const float4*)&K[t * 64];
        float dot = 0.f;
        #pragma unroll
        for (int j = 0; j < 16; j++) {
            float4 a = qp[j], c = kp[j];
            dot += a.x * c.x + a.y * c.y + a.z * c.z + a.w * c.w;
        }
        P[i] = __expf(dot * 0.125f);
    }
    __syncthreads();
    if (tid < 12) {
        float s = 0.f;
        #pragma unroll
        for (int j = 0; j < 24; j++) s += P[tid * 24 + j];
        Pinv[tid] = 1.f / s;
    }
    __syncthreads();
    for (int i = tid; i < 768; i += 128) {
        int s = i >> 6, d = i & 63;
        float acc = 0.f;
        #pragma unroll
        for (int t = 0; t < 24; t++) acc += P[s * 24 + t] * V[t * 64 + d];
        TGX[i] = acc * Pinv[s];
    }
    __syncthreads();
    for (int i = tid; i < 1536; i += 128) {
        int t = i >> 6, d = i & 63;
        const float* tm = &tmp_map[(((size_t)b * NN + n) * NT + t) * 12];
        float acc = 0.f;
        #pragma unroll
        for (int s = 0; s < 12; s++) acc += tm[s] * TGX[s * 64 + d];
        g_ST[((size_t)(b * NT + t) * NN + n) * 640 + 512 + h * 64 + d] = acc;
    }
}

// ---------------- host launcher ----------------
extern "C" void kernel_launch(void* const* d_in, const int* in_sizes, int n_in,
                              void* d_out, int out_size)
{
    (void)in_sizes; (void)n_in; (void)out_size;
    const float* x       = (const float*)d_in[0];
    const float* agg_x0  = (const float*)d_in[1];
    const float* agg_x1  = (const float*)d_in[2];
    const float* tmp_map = (const float*)d_in[3];
    const float* lq1 = (const float*)d_in[7];
    const float* lk1 = (const float*)d_in[8];
    const float* lq2 = (const float*)d_in[9];
    const float* lk2 = (const float*)d_in[10];
    const float* ln_g = (const float*)d_in[11];
    const float* ln_b = (const float*)d_in[12];
    const float* M0   = (const float*)d_in[19];
    const float* M1   = (const float*)d_in[20];
    const float* Wagg = (const float*)d_in[21];
    const float* bagg = (const float*)d_in[22];
    const float* q_agg = (const float*)d_in[26];
    const float* Wout  = (const float*)d_in[29];
    const float* bout  = (const float*)d_in[30];
    float* out = (float*)d_out;

    // pack x-projection weights into g_W: [q_s k_s v_s q_t k_t v_t k_tg v_tg]
    const size_t S256 = (size_t)256 * 512 * 4, S128 = (size_t)128 * 512 * 4;
    cudaMemcpyToSymbolAsync(g_W, d_in[4],  S256, 0,                    cudaMemcpyDeviceToDevice, 0);
    cudaMemcpyToSymbolAsync(g_W, d_in[5],  S256, S256,                 cudaMemcpyDeviceToDevice, 0);
    cudaMemcpyToSymbolAsync(g_W, d_in[6],  S256, 2 * S256,             cudaMemcpyDeviceToDevice, 0);
    cudaMemcpyToSymbolAsync(g_W, d_in[23], S128, 3 * S256,             cudaMemcpyDeviceToDevice, 0);
    cudaMemcpyToSymbolAsync(g_W, d_in[24], S128, 3 * S256 + S128,      cudaMemcpyDeviceToDevice, 0);
    cudaMemcpyToSymbolAsync(g_W, d_in[25], S128, 3 * S256 + 2 * S128,  cudaMemcpyDeviceToDevice, 0);
    cudaMemcpyToSymbolAsync(g_W, d_in[27], S128, 3 * S256 + 3 * S128,  cudaMemcpyDeviceToDevice, 0);
    cudaMemcpyToSymbolAsync(g_W, d_in[28], S128, 3 * S256 + 4 * S128,  cudaMemcpyDeviceToDevice, 0);
    // agg weights
    cudaMemcpyToSymbolAsync(g_Wa0, d_in[13], S128, 0,        cudaMemcpyDeviceToDevice, 0);
    cudaMemcpyToSymbolAsync(g_Wa0, d_in[14], S128, S128,     cudaMemcpyDeviceToDevice, 0);
    cudaMemcpyToSymbolAsync(g_Wa0, d_in[15], S128, 2 * S128, cudaMemcpyDeviceToDevice, 0);
    cudaMemcpyToSymbolAsync(g_Wa1, d_in[16], S128, 0,        cudaMemcpyDeviceToDevice, 0);
    cudaMemcpyToSymbolAsync(g_Wa1, d_in[17], S128, S128,     cudaMemcpyDeviceToDevice, 0);
    cudaMemcpyToSymbolAsync(g_Wa1, d_in[18], S128, 2 * S128, cudaMemcpyDeviceToDevice, 0);

    float *pW, *pWa0, *pWa1, *pQKV, *pAGP0, *pAGP1, *pSX0, *pSX1, *pSGP, *pST;
    cudaGetSymbolAddress((void**)&pW,    g_W);
    cudaGetSymbolAddress((void**)&pWa0,  g_Wa0);
    cudaGetSymbolAddress((void**)&pWa1,  g_Wa1);
    cudaGetSymbolAddress((void**)&pQKV,  g_QKV);
    cudaGetSymbolAddress((void**)&pAGP0, g_AGP0);
    cudaGetSymbolAddress((void**)&pAGP1, g_AGP1);
    cudaGetSymbolAddress((void**)&pSX0,  g_SX0);
    cudaGetSymbolAddress((void**)&pSX1,  g_SX1);
    cudaGetSymbolAddress((void**)&pSGP,  g_SGP);
    cudaGetSymbolAddress((void**)&pST,   g_ST);

    lambda_kernel<<<1, 32>>>(lq1, lk1, lq2, lk2);

    // projections
    sgemm_nt<<<dim3(395, 11), 256>>>(x,      512, pW,   512, pQKV,  LDQ, NBTN,  1408, 512, nullptr);
    sgemm_nt<<<dim3(48,  3),  256>>>(agg_x0, 512, pWa0, 512, pAGP0, 384, 6144,  384,  512, nullptr);
    sgemm_nt<<<dim3(96,  3),  256>>>(agg_x1, 512, pWa1, 512, pAGP1, 384, 12288, 384,  512, nullptr);

    // spatial differential attention
    const int SP_SMEM = (NN * 32 + NN * 64) * 4;   // 100992 B
    cudaFuncSetAttribute(spatial_attn, cudaFuncAttributeMaxDynamicSharedMemorySize, SP_SMEM);
    spatial_attn<<<dim3(NBT, 4, 2), 256, SP_SMEM>>>();
    combine_ln<<<(NBTN * 4) / 8, 256>>>(ln_g, ln_b);

    // aggregate branches
    agg_attn<<<dim3(NBT, 2), 64>>>(pAGP0, pSX0, 32);
    agg_attn<<<dim3(NBT, 2), 64>>>(pAGP1, pSX1, 64);
    agg_map<<<NBT, 256>>>(M0, M1);
    sgemm_nt<<<dim3(395, 1), 256>>>(pSGP, 128, Wagg, 128, pST + 256, 640, NBTN, 128, 128, bagg);

    // temporal branches
    temporal_attn<<<dim3(NB * NN, 2), 128>>>();
    tg_attn<<<dim3(NB * NN, 2), 128>>>(q_agg, tmp_map);

    // output projection
    sgemm_nt<<<dim3(395, 4), 256>>>(pST, 640, Wout, 640, out, 512, NBTN, 512, 640, bout);
}

// round 16
// speedup vs baseline: 1.0038x; 1.0038x over previous
#include <cuda_runtime.h>

// ---------------- problem constants ----------------
#define NB   8
#define NT   24
#define NN   263
#define ND   512
#define NBT  192          // B*T
#define NBTN 50496        // B*T*N
#define LDQ  1408         // packed qkv width

// packed QKV column offsets
#define C_QS   0
#define C_KS   256
#define C_VS   512
#define C_QT   768
#define C_KT   896
#define C_VT   1024
#define C_KTG  1152
#define C_VTG  1280

// ---------------- scratch (device globals; no allocation) ----------------
__device__ float g_W  [1408 * 512];
__device__ float g_Wa0[384 * 512];
__device__ float g_Wa1[384 * 512];
__device__ float g_QKV [(size_t)NBTN * LDQ];          // 284 MB
__device__ float g_AGP0[(size_t)NBT * 32 * 384];
__device__ float g_AGP1[(size_t)NBT * 64 * 384];
__device__ float g_ADIFF[(size_t)NBTN * 512];         // [btn][h(4)][br(2)][64]
__device__ float g_SX0[(size_t)NBT * 4096];           // [bt][h(2)][m(32)][64]
__device__ float g_SX1[(size_t)NBT * 8192];           // [bt][h(2)][m(64)][64]
__device__ float g_SGP[(size_t)NBTN * 128];
__device__ float g_ST [(size_t)NBTN * 640];           // 129 MB
__device__ float g_lambda;

// ---------------- lambda scalar ----------------
__global__ void lambda_kernel(const float* __restrict__ lq1, const float* __restrict__ lk1,
                              const float* __restrict__ lq2, const float* __restrict__ lk2) {
    int l = threadIdx.x;
    float a = lq1[l] * lk1[l];
    float b = lq2[l] * lk2[l];
    #pragma unroll
    for (int o = 16; o; o >>= 1) {
        a += __shfl_xor_sync(0xffffffffu, a, o);
        b += __shfl_xor_sync(0xffffffffu, b, o);
    }
    if (l == 0) g_lambda = expf(a) - expf(b) + 0.2f;   // LAMBDA_INIT = 0.2
}

// ---------------- generic SGEMM: C[M,Nc] = A[M,K] * B[Nc,K]^T (+bias) ----------------
// BM=BN=128, BK=16, 256 threads, 8x8 micro-tile. K % 16 == 0 required (true for 512/128/640).
__global__ __launch_bounds__(256) void sgemm_nt(
    const float* __restrict__ A, int lda,
    const float* __restrict__ Bw, int ldb,
    float* __restrict__ C, int ldc,
    int M, int Ncols, int K,
    const float* __restrict__ bias)
{
    __shared__ float As[16][132];
    __shared__ float Bs[16][132];
    const int tid = threadIdx.x;
    const int bm = blockIdx.x * 128;
    const int bn = blockIdx.y * 128;
    const int tx = tid & 15, ty = tid >> 4;

    float acc[8][8];
    #pragma unroll
    for (int i = 0; i < 8; i++)
        #pragma unroll
        for (int j = 0; j < 8; j++) acc[i][j] = 0.f;

    for (int k0 = 0; k0 < K; k0 += 16) {
        #pragma unroll
        for (int l = 0; l < 2; l++) {
            int i = tid + l * 256;
            int row = i >> 2;
            int kq  = (i & 3) << 2;
            float4 v = make_float4(0.f, 0.f, 0.f, 0.f);
            int gr = bm + row;
            if (gr < M) v = *(const float4*)&A[(size_t)gr * lda + k0 + kq];
            As[kq + 0][row] = v.x; As[kq + 1][row] = v.y;
            As[kq + 2][row] = v.z; As[kq + 3][row] = v.w;
        }
        #pragma unroll
        for (int l = 0; l < 2; l++) {
            int i = tid + l * 256;
            int col = i >> 2;
            int kq  = (i & 3) << 2;
            float4 v = make_float4(0.f, 0.f, 0.f, 0.f);
            int gc = bn + col;
            if (gc < Ncols) v = *(const float4*)&Bw[(size_t)gc * ldb + k0 + kq];
            Bs[kq + 0][col] = v.x; Bs[kq + 1][col] = v.y;
            Bs[kq + 2][col] = v.z; Bs[kq + 3][col] = v.w;
        }
        __syncthreads();
        #pragma unroll
        for (int k = 0; k < 16; k++) {
            float4 a0 = *(const float4*)&As[k][ty * 8];
            float4 a1 = *(const float4*)&As[k][ty * 8 + 4];
            float4 b0 = *(const float4*)&Bs[k][tx * 8];
            float4 b1 = *(const float4*)&Bs[k][tx * 8 + 4];
            float av[8] = {a0.x, a0.y, a0.z, a0.w, a1.x, a1.y, a1.z, a1.w};
            float bv[8] = {b0.x, b0.y, b0.z, b0.w, b1.x, b1.y, b1.z, b1.w};
            #pragma unroll
            for (int i = 0; i < 8; i++)
                #pragma unroll
                for (int j = 0; j < 8; j++) acc[i][j] += av[i] * bv[j];
        }
        __syncthreads();
    }

    float bsv[8];
    #pragma unroll
    for (int j = 0; j < 8; j++) {
        int col = bn + tx * 8 + j;
        bsv[j] = (bias != nullptr && col < Ncols) ? bias[col] : 0.f;
    }
    #pragma unroll
    for (int i = 0; i < 8; i++) {
        int row = bm + ty * 8 + i;
        if (row >= M) continue;
        float* cp = &C[(size_t)row * ldc + bn + tx * 8];
        if (bn + tx * 8 + 7 < Ncols) {
            float4 o0 = make_float4(acc[i][0] + bsv[0], acc[i][1] + bsv[1],
                                    acc[i][2] + bsv[2], acc[i][3] + bsv[3]);
            float4 o1 = make_float4(acc[i][4] + bsv[4], acc[i][5] + bsv[5],
                                    acc[i][6] + bsv[6], acc[i][7] + bsv[7]);
            *(float4*)cp       = o0;
            *(float4*)(cp + 4) = o1;
        } else {
            #pragma unroll
            for (int j = 0; j < 8; j++) {
                int col = bn + tx * 8 + j;
                if (col < Ncols) cp[j] = acc[i][j] + bsv[j];
            }
        }
    }
}

// ---------------- differential spatial attention ----------------
// grid (NBT, 4 heads, 2 branches), 256 threads, dyn smem: K(263*32)+V(263*64) floats.
__global__ __launch_bounds__(256) void spatial_attn()
{
    extern __shared__ float sh[];
    float* Ksh = sh;             // 263*32
    float* Vsh = sh + NN * 32;   // 263*64
    const int bt = blockIdx.x, h = blockIdx.y, br = blockIdx.z;
    const int tid = threadIdx.x;
    const size_t base = (size_t)bt * NN * LDQ;
    const int kcol = C_KS + h * 64 + br * 32;
    const int vcol = C_VS + h * 64;
    const int qcol = C_QS + h * 64 + br * 32;

    for (int i = tid; i < NN * 32; i += 256) {
        int n = i >> 5, d = i & 31;
        Ksh[i] = g_QKV[base + (size_t)n * LDQ + kcol + d];
    }
    for (int i = tid; i < NN * 64; i += 256) {
        int n = i >> 6, d = i & 63;
        Vsh[i] = g_QKV[base + (size_t)n * LDQ + vcol + d];
    }
    __syncthreads();

    const float sc = 0.17677669529663687f;  // 32^-0.5
    for (int qi = tid; qi < NN; qi += 256) {
        float4 q[8];
        const float4* qp = (const float4*)&g_QKV[base + (size_t)qi * LDQ + qcol];
        #pragma unroll
        for (int j = 0; j < 8; j++) q[j] = qp[j];

        float4 acc[16];
        #pragma unroll
        for (int j = 0; j < 16; j++) acc[j] = make_float4(0.f, 0.f, 0.f, 0.f);
        float s = 0.f;

        for (int key = 0; key < NN; key++) {
            const float4* kp = (const float4*)&Ksh[key * 32];
            float dot = 0.f;
            #pragma unroll
            for (int j = 0; j < 8; j++) {
                float4 kv = kp[j];
                dot += q[j].x * kv.x + q[j].y * kv.y + q[j].z * kv.z + q[j].w * kv.w;
            }
            float p = __expf(dot * sc);
            s += p;
            const float4* vp = (const float4*)&Vsh[key * 64];
            #pragma unroll
            for (int j = 0; j < 16; j++) {
                float4 vv = vp[j];
                acc[j].x += p * vv.x; acc[j].y += p * vv.y;
                acc[j].z += p * vv.z; acc[j].w += p * vv.w;
            }
        }
        float inv = 1.f / s;
        float* o = &g_ADIFF[(((size_t)(bt * NN + qi) * 4 + h) * 2 + br) * 64];
        #pragma unroll
        for (int j = 0; j < 16; j++) {
            float4 ov = make_float4(acc[j].x * inv, acc[j].y * inv,
                                    acc[j].z * inv, acc[j].w * inv);
            *(float4*)&o[j * 4] = ov;
        }
    }
}

// ---------------- combine a1 - lam*a2, LayerNorm(64), *0.8 -> ST[:,0:256] ----------------
__global__ __launch_bounds__(256) void combine_ln(const float* __restrict__ lng,
                                                  const float* __restrict__ lnb)
{
    int gw = (blockIdx.x * 256 + threadIdx.x) >> 5;
    int lane = threadIdx.x & 31;
    if (gw >= NBTN * 4) return;
    const float* a = &g_ADIFF[(size_t)gw * 128];
    float lam = g_lambda;
    float y0 = a[lane]      - lam * a[lane + 64];
    float y1 = a[lane + 32] - lam * a[lane + 96];
    float s = y0 + y1, q = y0 * y0 + y1 * y1;
    #pragma unroll
    for (int o = 16; o; o >>= 1) {
        s += __shfl_xor_sync(0xffffffffu, s, o);
        q += __shfl_xor_sync(0xffffffffu, q, o);
    }
    float m   = s * (1.f / 64.f);
    float var = q * (1.f / 64.f) - m * m;
    float r   = rsqrtf(var + 1e-5f);
    int btn = gw >> 2, h = gw & 3;
    float* o = &g_ST[(size_t)btn * 640 + h * 64];
    o[lane]      = ((y0 - m) * r * lng[lane]      + lnb[lane])      * 0.8f;
    o[lane + 32] = ((y1 - m) * r * lng[lane + 32] + lnb[lane + 32]) * 0.8f;
}

// ---------------- aggregate-branch attention (Ni keys/queries, dha=64) ----------------
__global__ __launch_bounds__(64) void agg_attn(const float* __restrict__ AGP,
                                               float* __restrict__ SX, int Ni)
{
    __shared__ float Ksh[64 * 64];
    __shared__ float Vsh[64 * 64];
    const int bt = blockIdx.x, h = blockIdx.y, tid = threadIdx.x;
    const size_t base = (size_t)bt * Ni * 384;
    for (int i = tid; i < Ni * 64; i += 64) {
        int m = i >> 6, d = i & 63;
        Ksh[i] = AGP[base + (size_t)m * 384 + 128 + h * 64 + d];
        Vsh[i] = AGP[base + (size_t)m * 384 + 256 + h * 64 + d];
    }
    __syncthreads();
    if (tid < Ni) {
        float4 q[16];
        const float4* qp = (const float4*)&AGP[base + (size_t)tid * 384 + h * 64];
        #pragma unroll
        for (int j = 0; j < 16; j++) q[j] = qp[j];
        float4 acc[16];
        #pragma unroll
        for (int j = 0; j < 16; j++) acc[j] = make_float4(0.f, 0.f, 0.f, 0.f);
        float s = 0.f;
        for (int key = 0; key < Ni; key++) {
            const float4* kp = (const float4*)&Ksh[key * 64];
            float dot = 0.f;
            #pragma unroll
            for (int j = 0; j < 16; j++) {
                float4 kv = kp[j];
                dot += q[j].x * kv.x + q[j].y * kv.y + q[j].z * kv.z + q[j].w * kv.w;
            }
            float p = __expf(dot * 0.125f);
            s += p;
            const float4* vp = (const float4*)&Vsh[key * 64];
            #pragma unroll
            for (int j = 0; j < 16; j++) {
                float4 vv = vp[j];
                acc[j].x += p * vv.x; acc[j].y += p * vv.y;
                acc[j].z += p * vv.z; acc[j].w += p * vv.w;
            }
        }
        float inv = 1.f / s;
        float* o = &SX[((size_t)(bt * 2 + h) * Ni + tid) * 64];
        #pragma unroll
        for (int j = 0; j < 16; j++)
            *(float4*)&o[j * 4] = make_float4(acc[j].x * inv, acc[j].y * inv,
                                              acc[j].z * inv, acc[j].w * inv);
    }
}

// ---------------- map agg branches to N via M0/M1 -> SGP ----------------
__global__ __launch_bounds__(256) void agg_map(const float* __restrict__ M0,
                                               const float* __restrict__ M1)
{
    __shared__ float s0[4096];
    __shared__ float s1[8192];
    const int bt = blockIdx.x, tid = threadIdx.x;
    const float* src0 = g_SX0 + (size_t)bt * 4096;
    const float* src1 = g_SX1 + (size_t)bt * 8192;
    for (int i = tid; i < 4096; i += 256) s0[i] = src0[i];
    for (int i = tid; i < 8192; i += 256) s1[i] = src1[i];
    __syncthreads();
    for (int g = tid; g < NN * 32; g += 256) {
        int n = g >> 5;
        int c = (g & 31) << 2;   // 0..124, 4-wide groups (never straddle h)
        int h = c >> 6, d = c & 63;
        float4 acc = make_float4(0.f, 0.f, 0.f, 0.f);
        const float* p0 = &s0[h * 2048 + d];
        #pragma unroll
        for (int m = 0; m < 32; m++) {
            float w = M0[m * NN + n];
            float4 v = *(const float4*)&p0[m * 64];
            acc.x += w * v.x; acc.y += w * v.y; acc.z += w * v.z; acc.w += w * v.w;
        }
        const float* p1 = &s1[h * 4096 + d];
        #pragma unroll
        for (int m = 0; m < 64; m++) {
            float w = M1[m * NN + n];
            float4 v = *(const float4*)&p1[m * 64];
            acc.x += w * v.x; acc.y += w * v.y; acc.z += w * v.z; acc.w += w * v.w;
        }
        *(float4*)&g_SGP[(size_t)(bt * NN + n) * 128 + c] = acc;
    }
}

// ---------------- temporal attention over T=24 -> ST[:,384:512] ----------------
__global__ __launch_bounds__(128) void temporal_attn()
{
    __shared__ float Q[24 * 64], K[24 * 64], V[24 * 64], P[24 * 24], Pinv[24];
    const int b = blockIdx.x / NN, n = blockIdx.x % NN, h = blockIdx.y;
    const int tid = threadIdx.x;
    for (int i = tid; i < 24 * 64; i += 128) {
        int t = i >> 6, d = i & 63;
        size_t row = ((size_t)(b * NT + t) * NN + n) * LDQ;
        Q[i] = g_QKV[row + C_QT + h * 64 + d];
        K[i] = g_QKV[row + C_KT + h * 64 + d];
        V[i] = g_QKV[row + C_VT + h * 64 + d];
    }
    __syncthreads();
    for (int i = tid; i < 576; i += 128) {
        int tq = i / 24, ts = i % 24;
        const float4* qp = (const float4*)&Q[tq * 64];
        const float4* kp = (const float4*)&K[ts * 64];
        float dot = 0.f;
        #pragma unroll
        for (int j = 0; j < 16; j++) {
            float4 a = qp[j], c = kp[j];
            dot += a.x * c.x + a.y * c.y + a.z * c.z + a.w * c.w;
        }
        P[i] = __expf(dot * 0.125f);
    }
    __syncthreads();
    if (tid < 24) {
        float s = 0.f;
        #pragma unroll
        for (int j = 0; j < 24; j++) s += P[tid * 24 + j];
        Pinv[tid] = 1.f / s;
    }
    __syncthreads();
    for (int i = tid; i < 1536; i += 128) {
        int tq = i >> 6, d = i & 63;
        float acc = 0.f;
        #pragma unroll
        for (int s = 0; s < 24; s++) acc += P[tq * 24 + s] * V[s * 64 + d];
        g_ST[((size_t)(b * NT + tq) * NN + n) * 640 + 384 + h * 64 + d] = acc * Pinv[tq];
    }
}

// ---------------- temporal aggregation tg -> ST[:,512:640] ----------------
__global__ __launch_bounds__(128) void tg_attn(const float* __restrict__ q_agg,
                                               const float* __restrict__ tmp_map)
{
    __shared__ float Qg[12 * 64], K[24 * 64], V[24 * 64], P[12 * 24], TGX[12 * 64], Pinv[12];
    const int b = blockIdx.x / NN, n = blockIdx.x % NN, h = blockIdx.y;
    const int tid = threadIdx.x;
    for (int i = tid; i < 24 * 64; i += 128) {
        int t = i >> 6, d = i & 63;
        size_t row = ((size_t)(b * NT + t) * NN + n) * LDQ;
        K[i] = g_QKV[row + C_KTG + h * 64 + d];
        V[i] = g_QKV[row + C_VTG + h * 64 + d];
    }
    for (int i = tid; i < 12 * 64; i += 128) {
        int s = i >> 6, d = i & 63;
        Qg[i] = q_agg[((size_t)n * 12 + s) * 128 + h * 64 + d];
    }
    __syncthreads();
    for (int i = tid; i < 288; i += 128) {
        int s = i / 24, t = i % 24;
        const float4* qp = (const float4*)&Qg[s * 64];
        const float4* kp = (const float4*)&K[t * 64];
        float dot = 0.f;
        #pragma unroll
        for (int j = 0; j < 16; j++) {
            float4 a = qp[j], c = kp[j];
            dot += a.x * c.x + a.y * c.y + a.z * c.z + a.w * c.w;
        }
        P[i] = __expf(dot * 0.125f);
    }
    __syncthreads();
    if (tid < 12) {
        float s = 0.f;
        #pragma unroll
        for (int j = 0; j < 24; j++) s += P[tid * 24 + j];
        Pinv[tid] = 1.f / s;
    }
    __syncthreads();
    for (int i = tid; i < 768; i += 128) {
        int s = i >> 6, d = i & 63;
        float acc = 0.f;
        #pragma unroll
        for (int t = 0; t < 24; t++) acc += P[s * 24 + t] * V[t * 64 + d];
        TGX[i] = acc * Pinv[s];
    }
    __syncthreads();
    for (int i = tid; i < 1536; i += 128) {
        int t = i >> 6, d = i & 63;
        const float* tm = &tmp_map[(((size_t)b * NN + n) * NT + t) * 12];
        float acc = 0.f;
        #pragma unroll
        for (int s = 0; s < 12; s++) acc += tm[s] * TGX[s * 64 + d];
        g_ST[((size_t)(b * NT + t) * NN + n) * 640 + 512 + h * 64 + d] = acc;
    }
}

// ---------------- host launcher ----------------
extern "C" void kernel_launch(void* const* d_in, const int* in_sizes, int n_in,
                              void* d_out, int out_size)
{
    (void)in_sizes; (void)n_in; (void)out_size;
    const float* x       = (const float*)d_in[0];
    const float* agg_x0  = (const float*)d_in[1];
    const float* agg_x1  = (const float*)d_in[2];
    const float* tmp_map = (const float*)d_in[3];
    const float* lq1 = (const float*)d_in[7];
    const float* lk1 = (const float*)d_in[8];
    const float* lq2 = (const float*)d_in[9];
    const float* lk2 = (const float*)d_in[10];
    const float* ln_g = (const float*)d_in[11];
    const float* ln_b = (const float*)d_in[12];
    const float* M0   = (const float*)d_in[19];
    const float* M1   = (const float*)d_in[20];
    const float* Wagg = (const float*)d_in[21];
    const float* bagg = (const float*)d_in[22];
    const float* q_agg = (const float*)d_in[26];
    const float* Wout  = (const float*)d_in[29];
    const float* bout  = (const float*)d_in[30];
    float* out = (float*)d_out;

    // pack x-projection weights into g_W: [q_s k_s v_s q_t k_t v_t k_tg v_tg]
    const size_t S256 = (size_t)256 * 512 * 4, S128 = (size_t)128 * 512 * 4;
    cudaMemcpyToSymbolAsync(g_W, d_in[4],  S256, 0,                    cudaMemcpyDeviceToDevice, 0);
    cudaMemcpyToSymbolAsync(g_W, d_in[5],  S256, S256,                 cudaMemcpyDeviceToDevice, 0);
    cudaMemcpyToSymbolAsync(g_W, d_in[6],  S256, 2 * S256,             cudaMemcpyDeviceToDevice, 0);
    cudaMemcpyToSymbolAsync(g_W, d_in[23], S128, 3 * S256,             cudaMemcpyDeviceToDevice, 0);
    cudaMemcpyToSymbolAsync(g_W, d_in[24], S128, 3 * S256 + S128,      cudaMemcpyDeviceToDevice, 0);
    cudaMemcpyToSymbolAsync(g_W, d_in[25], S128, 3 * S256 + 2 * S128,  cudaMemcpyDeviceToDevice, 0);
    cudaMemcpyToSymbolAsync(g_W, d_in[27], S128, 3 * S256 + 3 * S128,  cudaMemcpyDeviceToDevice, 0);
    cudaMemcpyToSymbolAsync(g_W, d_in[28], S128, 3 * S256 + 4 * S128,  cudaMemcpyDeviceToDevice, 0);
    // agg weights
    cudaMemcpyToSymbolAsync(g_Wa0, d_in[13], S128, 0,        cudaMemcpyDeviceToDevice, 0);
    cudaMemcpyToSymbolAsync(g_Wa0, d_in[14], S128, S128,     cudaMemcpyDeviceToDevice, 0);
    cudaMemcpyToSymbolAsync(g_Wa0, d_in[15], S128, 2 * S128, cudaMemcpyDeviceToDevice, 0);
    cudaMemcpyToSymbolAsync(g_Wa1, d_in[16], S128, 0,        cudaMemcpyDeviceToDevice, 0);
    cudaMemcpyToSymbolAsync(g_Wa1, d_in[17], S128, S128,     cudaMemcpyDeviceToDevice, 0);
    cudaMemcpyToSymbolAsync(g_Wa1, d_in[18], S128, 2 * S128, cudaMemcpyDeviceToDevice, 0);

    float *pW, *pWa0, *pWa1, *pQKV, *pAGP0, *pAGP1, *pSX0, *pSX1, *pSGP, *pST;
    cudaGetSymbolAddress((void**)&pW,    g_W);
    cudaGetSymbolAddress((void**)&pWa0,  g_Wa0);
    cudaGetSymbolAddress((void**)&pWa1,  g_Wa1);
    cudaGetSymbolAddress((void**)&pQKV,  g_QKV);
    cudaGetSymbolAddress((void**)&pAGP0, g_AGP0);
    cudaGetSymbolAddress((void**)&pAGP1, g_AGP1);
    cudaGetSymbolAddress((void**)&pSX0,  g_SX0);
    cudaGetSymbolAddress((void**)&pSX1,  g_SX1);
    cudaGetSymbolAddress((void**)&pSGP,  g_SGP);
    cudaGetSymbolAddress((void**)&pST,   g_ST);

    lambda_kernel<<<1, 32>>>(lq1, lk1, lq2, lk2);

    // projections
    sgemm_nt<<<dim3(395, 11), 256>>>(x,      512, pW,   512, pQKV,  LDQ, NBTN,  1408, 512, nullptr);
    sgemm_nt<<<dim3(48,  3),  256>>>(agg_x0, 512, pWa0, 512, pAGP0, 384, 6144,  384,  512, nullptr);
    sgemm_nt<<<dim3(96,  3),  256>>>(agg_x1, 512, pWa1, 512, pAGP1, 384, 12288, 384,  512, nullptr);

    // spatial differential attention
    const int SP_SMEM = (NN * 32 + NN * 64) * 4;   // 100992 B
    cudaFuncSetAttribute(spatial_attn, cudaFuncAttributeMaxDynamicSharedMemorySize, SP_SMEM);
    spatial_attn<<<dim3(NBT, 4, 2), 256, SP_SMEM>>>();
    combine_ln<<<(NBTN * 4) / 8, 256>>>(ln_g, ln_b);

    // aggregate branches
    agg_attn<<<dim3(NBT, 2), 64>>>(pAGP0, pSX0, 32);
    agg_attn<<<dim3(NBT, 2), 64>>>(pAGP1, pSX1, 64);
    agg_map<<<NBT, 256>>>(M0, M1);
    sgemm_nt<<<dim3(395, 1), 256>>>(pSGP, 128, Wagg, 128, pST + 256, 640, NBTN, 128, 128, bagg);

    // temporal branches
    temporal_attn<<<dim3(NB * NN, 2), 128>>>();
    tg_attn<<<dim3(NB * NN, 2), 128>>>(q_agg, tmp_map);

    // output projection
    sgemm_nt<<<dim3(395, 4), 256>>>(pST, 640, Wout, 640, out, 512, NBTN, 512, 640, bout);
}

// round 17
// speedup vs baseline: 1.0068x; 1.0030x over previous
#include <cuda_runtime.h>

// ---------------- problem constants ----------------
#define NB   8
#define NT   24
#define NN   263
#define ND   512
#define NBT  192          // B*T
#define NBTN 50496        // B*T*N
#define LDQ  1408         // packed qkv width

// packed QKV column offsets
#define C_QS   0
#define C_KS   256
#define C_VS   512
#define C_QT   768
#define C_KT   896
#define C_VT   1024
#define C_KTG  1152
#define C_VTG  1280

// ---------------- scratch (device globals; no allocation) ----------------
__device__ float g_W  [1408 * 512];
__device__ float g_Wa0[384 * 512];
__device__ float g_Wa1[384 * 512];
__device__ float g_QKV [(size_t)NBTN * LDQ];          // 284 MB
__device__ float g_AGP0[(size_t)NBT * 32 * 384];
__device__ float g_AGP1[(size_t)NBT * 64 * 384];
__device__ float g_ADIFF[(size_t)NBTN * 512];         // [btn][h(4)][br(2)][64]
__device__ float g_SX0[(size_t)NBT * 4096];           // [bt][h(2)][m(32)][64]
__device__ float g_SX1[(size_t)NBT * 8192];           // [bt][h(2)][m(64)][64]
__device__ float g_SGP[(size_t)NBTN * 128];
__device__ float g_ST [(size_t)NBTN * 640];           // 129 MB
__device__ float g_lambda;

// ---------------- lambda scalar ----------------
__global__ void lambda_kernel(const float* __restrict__ lq1, const float* __restrict__ lk1,
                              const float* __restrict__ lq2, const float* __restrict__ lk2) {
    int l = threadIdx.x;
    float a = lq1[l] * lk1[l];
    float b = lq2[l] * lk2[l];
    #pragma unroll
    for (int o = 16; o; o >>= 1) {
        a += __shfl_xor_sync(0xffffffffu, a, o);
        b += __shfl_xor_sync(0xffffffffu, b, o);
    }
    if (l == 0) g_lambda = expf(a) - expf(b) + 0.2f;   // LAMBDA_INIT = 0.2
}

// ---------------- generic SGEMM: C[M,Nc] = A[M,K] * B[Nc,K]^T (+bias) ----------------
// BM=BN=128, BK=16, 256 threads, 8x8 micro-tile. K % 16 == 0 required (true for 512/128/640).
__global__ __launch_bounds__(256) void sgemm_nt(
    const float* __restrict__ A, int lda,
    const float* __restrict__ Bw, int ldb,
    float* __restrict__ C, int ldc,
    int M, int Ncols, int K,
    const float* __restrict__ bias)
{
    __shared__ float As[16][132];
    __shared__ float Bs[16][132];
    const int tid = threadIdx.x;
    const int bm = blockIdx.x * 128;
    const int bn = blockIdx.y * 128;
    const int tx = tid & 15, ty = tid >> 4;

    float acc[8][8];
    #pragma unroll
    for (int i = 0; i < 8; i++)
        #pragma unroll
        for (int j = 0; j < 8; j++) acc[i][j] = 0.f;

    for (int k0 = 0; k0 < K; k0 += 16) {
        #pragma unroll
        for (int l = 0; l < 2; l++) {
            int i = tid + l * 256;
            int row = i >> 2;
            int kq  = (i & 3) << 2;
            float4 v = make_float4(0.f, 0.f, 0.f, 0.f);
            int gr = bm + row;
            if (gr < M) v = *(const float4*)&A[(size_t)gr * lda + k0 + kq];
            As[kq + 0][row] = v.x; As[kq + 1][row] = v.y;
            As[kq + 2][row] = v.z; As[kq + 3][row] = v.w;
        }
        #pragma unroll
        for (int l = 0; l < 2; l++) {
            int i = tid + l * 256;
            int col = i >> 2;
            int kq  = (i & 3) << 2;
            float4 v = make_float4(0.f, 0.f, 0.f, 0.f);
            int gc = bn + col;
            if (gc < Ncols) v = *(const float4*)&Bw[(size_t)gc * ldb + k0 + kq];
            Bs[kq + 0][col] = v.x; Bs[kq + 1][col] = v.y;
            Bs[kq + 2][col] = v.z; Bs[kq + 3][col] = v.w;
        }
        __syncthreads();
        #pragma unroll
        for (int k = 0; k < 16; k++) {
            float4 a0 = *(const float4*)&As[k][ty * 8];
            float4 a1 = *(const float4*)&As[k][ty * 8 + 4];
            float4 b0 = *(const float4*)&Bs[k][tx * 8];
            float4 b1 = *(const float4*)&Bs[k][tx * 8 + 4];
            float av[8] = {a0.x, a0.y, a0.z, a0.w, a1.x, a1.y, a1.z, a1.w};
            float bv[8] = {b0.x, b0.y, b0.z, b0.w, b1.x, b1.y, b1.z, b1.w};
            #pragma unroll
            for (int i = 0; i < 8; i++)
                #pragma unroll
                for (int j = 0; j < 8; j++) acc[i][j] += av[i] * bv[j];
        }
        __syncthreads();
    }

    float bsv[8];
    #pragma unroll
    for (int j = 0; j < 8; j++) {
        int col = bn + tx * 8 + j;
        bsv[j] = (bias != nullptr && col < Ncols) ? bias[col] : 0.f;
    }
    #pragma unroll
    for (int i = 0; i < 8; i++) {
        int row = bm + ty * 8 + i;
        if (row >= M) continue;
        float* cp = &C[(size_t)row * ldc + bn + tx * 8];
        if (bn + tx * 8 + 7 < Ncols) {
            float4 o0 = make_float4(acc[i][0] + bsv[0], acc[i][1] + bsv[1],
                                    acc[i][2] + bsv[2], acc[i][3] + bsv[3]);
            float4 o1 = make_float4(acc[i][4] + bsv[4], acc[i][5] + bsv[5],
                                    acc[i][6] + bsv[6], acc[i][7] + bsv[7]);
            *(float4*)cp       = o0;
            *(float4*)(cp + 4) = o1;
        } else {
            #pragma unroll
            for (int j = 0; j < 8; j++) {
                int col = bn + tx * 8 + j;
                if (col < Ncols) cp[j] = acc[i][j] + bsv[j];
            }
        }
    }
}

// ---------------- differential spatial attention ----------------
// grid (NBT, 4 heads, 2 branches), 256 threads, dyn smem: K(263*32)+V(263*64) floats.
__global__ __launch_bounds__(256) void spatial_attn()
{
    extern __shared__ float sh[];
    float* Ksh = sh;             // 263*32
    float* Vsh = sh + NN * 32;   // 263*64
    const int bt = blockIdx.x, h = blockIdx.y, br = blockIdx.z;
    const int tid = threadIdx.x;
    const size_t base = (size_t)bt * NN * LDQ;
    const int kcol = C_KS + h * 64 + br * 32;
    const int vcol = C_VS + h * 64;
    const int qcol = C_QS + h * 64 + br * 32;

    for (int i = tid; i < NN * 32; i += 256) {
        int n = i >> 5, d = i & 31;
        Ksh[i] = g_QKV[base + (size_t)n * LDQ + kcol + d];
    }
    for (int i = tid; i < NN * 64; i += 256) {
        int n = i >> 6, d = i & 63;
        Vsh[i] = g_QKV[base + (size_t)n * LDQ + vcol + d];
    }
    __syncthreads();

    const float sc = 0.17677669529663687f;  // 32^-0.5
    for (int qi = tid; qi < NN; qi += 256) {
        float4 q[8];
        const float4* qp = (const float4*)&g_QKV[base + (size_t)qi * LDQ + qcol];
        #pragma unroll
        for (int j = 0; j < 8; j++) q[j] = qp[j];

        float4 acc[16];
        #pragma unroll
        for (int j = 0; j < 16; j++) acc[j] = make_float4(0.f, 0.f, 0.f, 0.f);
        float s = 0.f;

        for (int key = 0; key < NN; key++) {
            const float4* kp = (const float4*)&Ksh[key * 32];
            float dot = 0.f;
            #pragma unroll
            for (int j = 0; j < 8; j++) {
                float4 kv = kp[j];
                dot += q[j].x * kv.x + q[j].y * kv.y + q[j].z * kv.z + q[j].w * kv.w;
            }
            float p = __expf(dot * sc);
            s += p;
            const float4* vp = (const float4*)&Vsh[key * 64];
            #pragma unroll
            for (int j = 0; j < 16; j++) {
                float4 vv = vp[j];
                acc[j].x += p * vv.x; acc[j].y += p * vv.y;
                acc[j].z += p * vv.z; acc[j].w += p * vv.w;
            }
        }
        float inv = 1.f / s;
        float* o = &g_ADIFF[(((size_t)(bt * NN + qi) * 4 + h) * 2 + br) * 64];
        #pragma unroll
        for (int j = 0; j < 16; j++) {
            float4 ov = make_float4(acc[j].x * inv, acc[j].y * inv,
                                    acc[j].z * inv, acc[j].w * inv);
            *(float4*)&o[j * 4] = ov;
        }
    }
}

// ---------------- combine a1 - lam*a2, LayerNorm(64), *0.8 -> ST[:,0:256] ----------------
__global__ __launch_bounds__(256) void combine_ln(const float* __restrict__ lng,
                                                  const float* __restrict__ lnb)
{
    int gw = (blockIdx.x * 256 + threadIdx.x) >> 5;
    int lane = threadIdx.x & 31;
    if (gw >= NBTN * 4) return;
    const float* a = &g_ADIFF[(size_t)gw * 128];
    float lam = g_lambda;
    float y0 = a[lane]      - lam * a[lane + 64];
    float y1 = a[lane + 32] - lam * a[lane + 96];
    float s = y0 + y1, q = y0 * y0 + y1 * y1;
    #pragma unroll
    for (int o = 16; o; o >>= 1) {
        s += __shfl_xor_sync(0xffffffffu, s, o);
        q += __shfl_xor_sync(0xffffffffu, q, o);
    }
    float m   = s * (1.f / 64.f);
    float var = q * (1.f / 64.f) - m * m;
    float r   = rsqrtf(var + 1e-5f);
    int btn = gw >> 2, h = gw & 3;
    float* o = &g_ST[(size_t)btn * 640 + h * 64];
    o[lane]      = ((y0 - m) * r * lng[lane]      + lnb[lane])      * 0.8f;
    o[lane + 32] = ((y1 - m) * r * lng[lane + 32] + lnb[lane + 32]) * 0.8f;
}

// ---------------- aggregate-branch attention (Ni keys/queries, dha=64) ----------------
__global__ __launch_bounds__(64) void agg_attn(const float* __restrict__ AGP,
                                               float* __restrict__ SX, int Ni)
{
    __shared__ float Ksh[64 * 64];
    __shared__ float Vsh[64 * 64];
    const int bt = blockIdx.x, h = blockIdx.y, tid = threadIdx.x;
    const size_t base = (size_t)bt * Ni * 384;
    for (int i = tid; i < Ni * 64; i += 64) {
        int m = i >> 6, d = i & 63;
        Ksh[i] = AGP[base + (size_t)m * 384 + 128 + h * 64 + d];
        Vsh[i] = AGP[base + (size_t)m * 384 + 256 + h * 64 + d];
    }
    __syncthreads();
    if (tid < Ni) {
        float4 q[16];
        const float4* qp = (const float4*)&AGP[base + (size_t)tid * 384 + h * 64];
        #pragma unroll
        for (int j = 0; j < 16; j++) q[j] = qp[j];
        float4 acc[16];
        #pragma unroll
        for (int j = 0; j < 16; j++) acc[j] = make_float4(0.f, 0.f, 0.f, 0.f);
        float s = 0.f;
        for (int key = 0; key < Ni; key++) {
            const float4* kp = (const float4*)&Ksh[key * 64];
            float dot = 0.f;
            #pragma unroll
            for (int j = 0; j < 16; j++) {
                float4 kv = kp[j];
                dot += q[j].x * kv.x + q[j].y * kv.y + q[j].z * kv.z + q[j].w * kv.w;
            }
            float p = __expf(dot * 0.125f);
            s += p;
            const float4* vp = (const float4*)&Vsh[key * 64];
            #pragma unroll
            for (int j = 0; j < 16; j++) {
                float4 vv = vp[j];
                acc[j].x += p * vv.x; acc[j].y += p * vv.y;
                acc[j].z += p * vv.z; acc[j].w += p * vv.w;
            }
        }
        float inv = 1.f / s;
        float* o = &SX[((size_t)(bt * 2 + h) * Ni + tid) * 64];
        #pragma unroll
        for (int j = 0; j < 16; j++)
            *(float4*)&o[j * 4] = make_float4(acc[j].x * inv, acc[j].y * inv,
                                              acc[j].z * inv, acc[j].w * inv);
    }
}

// ---------------- map agg branches to N via M0/M1 -> SGP ----------------
__global__ __launch_bounds__(256) void agg_map(const float* __restrict__ M0,
                                               const float* __restrict__ M1)
{
    __shared__ float s0[4096];
    __shared__ float s1[8192];
    const int bt = blockIdx.x, tid = threadIdx.x;
    const float* src0 = g_SX0 + (size_t)bt * 4096;
    const float* src1 = g_SX1 + (size_t)bt * 8192;
    for (int i = tid; i < 4096; i += 256) s0[i] = src0[i];
    for (int i = tid; i < 8192; i += 256) s1[i] = src1[i];
    __syncthreads();
    for (int g = tid; g < NN * 32; g += 256) {
        int n = g >> 5;
        int c = (g & 31) << 2;   // 0..124, 4-wide groups (never straddle h)
        int h = c >> 6, d = c & 63;
        float4 acc = make_float4(0.f, 0.f, 0.f, 0.f);
        const float* p0 = &s0[h * 2048 + d];
        #pragma unroll
        for (int m = 0; m < 32; m++) {
            float w = M0[m * NN + n];
            float4 v = *(const float4*)&p0[m * 64];
            acc.x += w * v.x; acc.y += w * v.y; acc.z += w * v.z; acc.w += w * v.w;
        }
        const float* p1 = &s1[h * 4096 + d];
        #pragma unroll
        for (int m = 0; m < 64; m++) {
            float w = M1[m * NN + n];
            float4 v = *(const float4*)&p1[m * 64];
            acc.x += w * v.x; acc.y += w * v.y; acc.z += w * v.z; acc.w += w * v.w;
        }
        *(float4*)&g_SGP[(size_t)(bt * NN + n) * 128 + c] = acc;
    }
}

// ---------------- temporal attention over T=24 -> ST[:,384:512] ----------------
__global__ __launch_bounds__(128) void temporal_attn()
{
    __shared__ float Q[24 * 64], K[24 * 64], V[24 * 64], P[24 * 24], Pinv[24];
    const int b = blockIdx.x / NN, n = blockIdx.x % NN, h = blockIdx.y;
    const int tid = threadIdx.x;
    for (int i = tid; i < 24 * 64; i += 128) {
        int t = i >> 6, d = i & 63;
        size_t row = ((size_t)(b * NT + t) * NN + n) * LDQ;
        Q[i] = g_QKV[row + C_QT + h * 64 + d];
        K[i] = g_QKV[row + C_KT + h * 64 + d];
        V[i] = g_QKV[row + C_VT + h * 64 + d];
    }
    __syncthreads();
    for (int i = tid; i < 576; i += 128) {
        int tq = i / 24, ts = i % 24;
        const float4* qp = (const float4*)&Q[tq * 64];
        const float4* kp = (const float4*)&K[ts * 64];
        float dot = 0.f;
        #pragma unroll
        for (int j = 0; j < 16; j++) {
            float4 a = qp[j], c = kp[j];
            dot += a.x * c.x + a.y * c.y + a.z * c.z + a.w * c.w;
        }
        P[i] = __expf(dot * 0.125f);
    }
    __syncthreads();
    if (tid < 24) {
        float s = 0.f;
        #pragma unroll
        for (int j = 0; j < 24; j++) s += P[tid * 24 + j];
        Pinv[tid] = 1.f / s;
    }
    __syncthreads();
    for (int i = tid; i < 1536; i += 128) {
        int tq = i >> 6, d = i & 63;
        float acc = 0.f;
        #pragma unroll
        for (int s = 0; s < 24; s++) acc += P[tq * 24 + s] * V[s * 64 + d];
        g_ST[((size_t)(b * NT + tq) * NN + n) * 640 + 384 + h * 64 + d] = acc * Pinv[tq];
    }
}

// ---------------- temporal aggregation tg -> ST[:,512:640] ----------------
__global__ __launch_bounds__(128) void tg_attn(const float* __restrict__ q_agg,
                                               const float* __restrict__ tmp_map)
{
    __shared__ float Qg[12 * 64], K[24 * 64], V[24 * 64], P[12 * 24], TGX[12 * 64], Pinv[12];
    const int b = blockIdx.x / NN, n = blockIdx.x % NN, h = blockIdx.y;
    const int tid = threadIdx.x;
    for (int i = tid; i < 24 * 64; i += 128) {
        int t = i >> 6, d = i & 63;
        size_t row = ((size_t)(b * NT + t) * NN + n) * LDQ;
        K[i] = g_QKV[row + C_KTG + h * 64 + d];
        V[i] = g_QKV[row + C_VTG + h * 64 + d];
    }
    for (int i = tid; i < 12 * 64; i += 128) {
        int s = i >> 6, d = i & 63;
        Qg[i] = q_agg[((size_t)n * 12 + s) * 128 + h * 64 + d];
    }
    __syncthreads();
    for (int i = tid; i < 288; i += 128) {
        int s = i / 24, t = i % 24;
        const float4* qp = (const float4*)&Qg[s * 64];
        const float4* kp = (const float4*)&K[t * 64];
        float dot = 0.f;
        #pragma unroll
        for (int j = 0; j < 16; j++) {
            float4 a = qp[j], c = kp[j];
            dot += a.x * c.x + a.y * c.y + a.z * c.z + a.w * c.w;
        }
        P[i] = __expf(dot * 0.125f);
    }
    __syncthreads();
    if (tid < 12) {
        float s = 0.f;
        #pragma unroll
        for (int j = 0; j < 24; j++) s += P[tid * 24 + j];
        Pinv[tid] = 1.f / s;
    }
    __syncthreads();
    for (int i = tid; i < 768; i += 128) {
        int s = i >> 6, d = i & 63;
        float acc = 0.f;
        #pragma unroll
        for (int t = 0; t < 24; t++) acc += P[s * 24 + t] * V[t * 64 + d];
        TGX[i] = acc * Pinv[s];
    }
    __syncthreads();
    for (int i = tid; i < 1536; i += 128) {
        int t = i >> 6, d = i & 63;
        const float* tm = &tmp_map[(((size_t)b * NN + n) * NT + t) * 12];
        float acc = 0.f;
        #pragma unroll
        for (int s = 0; s < 12; s++) acc += tm[s] * TGX[s * 64 + d];
        g_ST[((size_t)(b * NT + t) * NN + n) * 640 + 512 + h * 64 + d] = acc;
    }
}

// ---------------- host launcher ----------------
extern "C" void kernel_launch(void* const* d_in, const int* in_sizes, int n_in,
                              void* d_out, int out_size)
{
    (void)in_sizes; (void)n_in; (void)out_size;
    const float* x       = (const float*)d_in[0];
    const float* agg_x0  = (const float*)d_in[1];
    const float* agg_x1  = (const float*)d_in[2];
    const float* tmp_map = (const float*)d_in[3];
    const float* lq1 = (const float*)d_in[7];
    const float* lk1 = (const float*)d_in[8];
    const float* lq2 = (const float*)d_in[9];
    const float* lk2 = (const float*)d_in[10];
    const float* ln_g = (const float*)d_in[11];
    const float* ln_b = (const float*)d_in[12];
    const float* M0   = (const float*)d_in[19];
    const float* M1   = (const float*)d_in[20];
    const float* Wagg = (const float*)d_in[21];
    const float* bagg = (const float*)d_in[22];
    const float* q_agg = (const float*)d_in[26];
    const float* Wout  = (const float*)d_in[29];
    const float* bout  = (const float*)d_in[30];
    float* out = (float*)d_out;

    // pack x-projection weights into g_W: [q_s k_s v_s q_t k_t v_t k_tg v_tg]
    const size_t S256 = (size_t)256 * 512 * 4, S128 = (size_t)128 * 512 * 4;
    cudaMemcpyToSymbolAsync(g_W, d_in[4],  S256, 0,                    cudaMemcpyDeviceToDevice, 0);
    cudaMemcpyToSymbolAsync(g_W, d_in[5],  S256, S256,                 cudaMemcpyDeviceToDevice, 0);
    cudaMemcpyToSymbolAsync(g_W, d_in[6],  S256, 2 * S256,             cudaMemcpyDeviceToDevice, 0);
    cudaMemcpyToSymbolAsync(g_W, d_in[23], S128, 3 * S256,             cudaMemcpyDeviceToDevice, 0);
    cudaMemcpyToSymbolAsync(g_W, d_in[24], S128, 3 * S256 + S128,      cudaMemcpyDeviceToDevice, 0);
    cudaMemcpyToSymbolAsync(g_W, d_in[25], S128, 3 * S256 + 2 * S128,  cudaMemcpyDeviceToDevice, 0);
    cudaMemcpyToSymbolAsync(g_W, d_in[27], S128, 3 * S256 + 3 * S128,  cudaMemcpyDeviceToDevice, 0);
    cudaMemcpyToSymbolAsync(g_W, d_in[28], S128, 3 * S256 + 4 * S128,  cudaMemcpyDeviceToDevice, 0);
    // agg weights
    cudaMemcpyToSymbolAsync(g_Wa0, d_in[13], S128, 0,        cudaMemcpyDeviceToDevice, 0);
    cudaMemcpyToSymbolAsync(g_Wa0, d_in[14], S128, S128,     cudaMemcpyDeviceToDevice, 0);
    cudaMemcpyToSymbolAsync(g_Wa0, d_in[15], S128, 2 * S128, cudaMemcpyDeviceToDevice, 0);
    cudaMemcpyToSymbolAsync(g_Wa1, d_in[16], S128, 0,        cudaMemcpyDeviceToDevice, 0);
    cudaMemcpyToSymbolAsync(g_Wa1, d_in[17], S128, S128,     cudaMemcpyDeviceToDevice, 0);
    cudaMemcpyToSymbolAsync(g_Wa1, d_in[18], S128, 2 * S128, cudaMemcpyDeviceToDevice, 0);

    float *pW, *pWa0, *pWa1, *pQKV, *pAGP0, *pAGP1, *pSX0, *pSX1, *pSGP, *pST;
    cudaGetSymbolAddress((void**)&pW,    g_W);
    cudaGetSymbolAddress((void**)&pWa0,  g_Wa0);
    cudaGetSymbolAddress((void**)&pWa1,  g_Wa1);
    cudaGetSymbolAddress((void**)&pQKV,  g_QKV);
    cudaGetSymbolAddress((void**)&pAGP0, g_AGP0);
    cudaGetSymbolAddress((void**)&pAGP1, g_AGP1);
    cudaGetSymbolAddress((void**)&pSX0,  g_SX0);
    cudaGetSymbolAddress((void**)&pSX1,  g_SX1);
    cudaGetSymbolAddress((void**)&pSGP,  g_SGP);
    cudaGetSymbolAddress((void**)&pST,   g_ST);

    lambda_kernel<<<1, 32>>>(lq1, lk1, lq2, lk2);

    // projections
    sgemm_nt<<<dim3(395, 11), 256>>>(x,      512, pW,   512, pQKV,  LDQ, NBTN,  1408, 512, nullptr);
    sgemm_nt<<<dim3(48,  3),  256>>>(agg_x0, 512, pWa0, 512, pAGP0, 384, 6144,  384,  512, nullptr);
    sgemm_nt<<<dim3(96,  3),  256>>>(agg_x1, 512, pWa1, 512, pAGP1, 384, 12288, 384,  512, nullptr);

    // spatial differential attention
    const int SP_SMEM = (NN * 32 + NN * 64) * 4;   // 100992 B
    cudaFuncSetAttribute(spatial_attn, cudaFuncAttributeMaxDynamicSharedMemorySize, SP_SMEM);
    spatial_attn<<<dim3(NBT, 4, 2), 256, SP_SMEM>>>();
    combine_ln<<<(NBTN * 4) / 8, 256>>>(ln_g, ln_b);

    // aggregate branches
    agg_attn<<<dim3(NBT, 2), 64>>>(pAGP0, pSX0, 32);
    agg_attn<<<dim3(NBT, 2), 64>>>(pAGP1, pSX1, 64);
    agg_map<<<NBT, 256>>>(M0, M1);
    sgemm_nt<<<dim3(395, 1), 256>>>(pSGP, 128, Wagg, 128, pST + 256, 640, NBTN, 128, 128, bagg);

    // temporal branches
    temporal_attn<<<dim3(NB * NN, 2), 128>>>();
    tg_attn<<<dim3(NB * NN, 2), 128>>>(q_agg, tmp_map);

    // output projection
    sgemm_nt<<<dim3(395, 4), 256>>>(pST, 640, Wout, 640, out, 512, NBTN, 512, 640, bout);
}